// round 1
// baseline (speedup 1.0000x reference)
#include <cuda_runtime.h>
#include <stdint.h>

#define B_ 16
#define P_ 25
#define S_ 1024
#define D_ 128
#define H_ 8
#define DH_ 16
#define DFF_ 512
#define BP_ (B_*P_)
#define SIGMA_ 0.1f
#define OMEGA_ 0.5f

// output layout (flat f32 concat of the reference tuple)
#define OFF_R    0
#define OFF_Z    51200
#define OFF_PRED 102400
#define OFF_W    102800
#define OFF_K    103200
#define OFF_V    52532000
#define OFF_I    104960800

// scratch (allocation-free: __device__ globals)
__device__ __align__(16) float g_knew[BP_*D_];
__device__ __align__(16) float g_vnew[BP_*D_];
__device__ float g_pred[BP_];
__device__ int   g_idx[BP_];

__device__ __forceinline__ uint32_t rotl32(uint32_t x, int d) {
    return (x << d) | (x >> (32 - d));
}

// Threefry-2x32 with key (0, 42)  [jax.random.key(42)]
__device__ __forceinline__ void threefry_0_42(uint32_t x0, uint32_t x1,
                                              uint32_t& o0, uint32_t& o1) {
    const uint32_t k0 = 0u, k1 = 42u;
    const uint32_t k2 = k0 ^ k1 ^ 0x1BD11BDAu;
    uint32_t v0 = x0 + k0, v1 = x1 + k1;
#define TF_R(r) { v0 += v1; v1 = rotl32(v1, r); v1 ^= v0; }
    TF_R(13) TF_R(15) TF_R(26) TF_R(6)
    v0 += k1; v1 += k2 + 1u;
    TF_R(17) TF_R(29) TF_R(16) TF_R(24)
    v0 += k2; v1 += k0 + 2u;
    TF_R(13) TF_R(15) TF_R(26) TF_R(6)
    v0 += k0; v1 += k1 + 3u;
    TF_R(17) TF_R(29) TF_R(16) TF_R(24)
    v0 += k1; v1 += k2 + 4u;
    TF_R(13) TF_R(15) TF_R(26) TF_R(6)
    v0 += k2; v1 += k0 + 5u;
#undef TF_R
    o0 = v0; o1 = v1;
}

// ---------------------------------------------------------------------------
// Kernel 1: per-(b,p) forward. 400 blocks x 256 threads.
// ---------------------------------------------------------------------------
__global__ void __launch_bounds__(256) fwd_kernel(
    const float* __restrict__ x, const float* __restrict__ K,
    const float* __restrict__ V,
    const float* __restrict__ Wq, const float* __restrict__ Wk,
    const float* __restrict__ Wv, const float* __restrict__ Wo,
    const float* __restrict__ W1, const float* __restrict__ b1,
    const float* __restrict__ W2, const float* __restrict__ b2,
    const float* __restrict__ Wout, const float* __restrict__ bout,
    const float* __restrict__ eps_k, const float* __restrict__ eps_v,
    const float* __restrict__ eps_z,
    const int* __restrict__ tp, float* __restrict__ out)
{
    __shared__ float sx[D_], sq[D_], sk[D_], sv[D_];
    __shared__ float sctx[D_], sctx2[D_], sz[D_], sh1[DFF_], sr[D_];
    __shared__ float sS[H_][S_];

    const int bp  = blockIdx.x;
    const int tid = threadIdx.x;
    const int t   = tp ? tp[0] : 512;

    if (tid < D_) sx[tid] = x[bp*D_ + tid];
    __syncthreads();

    // q, k, v projections (coalesced over output dim)
    if (tid < D_) {
        float aq = 0.f, ak = 0.f, av = 0.f;
        #pragma unroll 8
        for (int d = 0; d < D_; ++d) {
            float xv = sx[d];
            aq += xv * Wq[d*D_ + tid];
            ak += xv * Wk[d*D_ + tid];
            av += xv * Wv[d*D_ + tid];
        }
        ak += SIGMA_ * eps_k[bp*D_ + tid];
        av += SIGMA_ * eps_v[bp*D_ + tid];
        sq[tid] = aq; sk[tid] = ak; sv[tid] = av;
        g_knew[bp*D_ + tid] = ak;
        g_vnew[bp*D_ + tid] = av;
    }
    __syncthreads();

    // scores for s in [0, t): one K row (512B) per thread, vectorized
    const float4* Kbase = reinterpret_cast<const float4*>(K + (size_t)bp * S_ * D_);
    for (int s = tid; s < t; s += 256) {
        const float4* kr = Kbase + (size_t)s * 32;
        float acc[H_];
        #pragma unroll
        for (int h = 0; h < H_; ++h) acc[h] = 0.f;
        #pragma unroll
        for (int i = 0; i < 32; ++i) {
            float4 kv = kr[i];
            int h = i >> 2;
            acc[h] += sq[4*i+0]*kv.x + sq[4*i+1]*kv.y + sq[4*i+2]*kv.z + sq[4*i+3]*kv.w;
        }
        #pragma unroll
        for (int h = 0; h < H_; ++h) sS[h][s] = acc[h] * 0.25f;
    }
    // s == t uses the freshly computed k
    if (tid < H_) {
        float a = 0.f;
        #pragma unroll
        for (int d = 0; d < DH_; ++d) a += sq[tid*DH_ + d] * sk[tid*DH_ + d];
        sS[tid][t] = a * 0.25f;
    }
    __syncthreads();

    // softmax per head (warp h handles head h)
    {
        int h = tid >> 5, lane = tid & 31;
        float m = -3.4e38f;
        for (int s = lane; s <= t; s += 32) m = fmaxf(m, sS[h][s]);
        #pragma unroll
        for (int o = 16; o; o >>= 1) m = fmaxf(m, __shfl_xor_sync(0xffffffffu, m, o));
        float sum = 0.f;
        for (int s = lane; s <= t; s += 32) {
            float e = expf(sS[h][s] - m);
            sS[h][s] = e; sum += e;
        }
        #pragma unroll
        for (int o = 16; o; o >>= 1) sum += __shfl_xor_sync(0xffffffffu, sum, o);
        float inv = 1.f / sum;
        for (int s = lane; s <= t; s += 32) sS[h][s] *= inv;
    }
    __syncthreads();

    // ctx: two half-blocks interleave over s; V reads coalesced over dim
    {
        int dim = tid & 127, half = tid >> 7;
        int h = dim >> 4;
        const float* Vrow = V + (size_t)bp * S_ * D_ + dim;
        float c = 0.f;
        for (int s = half; s <= t; s += 2) {
            float vv = (s == t) ? sv[dim] : Vrow[(size_t)s * D_];
            c += sS[h][s] * vv;
        }
        if (half == 0) sctx[dim] = c; else sctx2[dim] = c;
    }
    __syncthreads();
    if (tid < D_) sctx[tid] += sctx2[tid];
    __syncthreads();

    // z = ctx @ Wo + sigma*eps_z
    if (tid < D_) {
        float a = 0.f;
        #pragma unroll 8
        for (int d = 0; d < D_; ++d) a += sctx[d] * Wo[d*D_ + tid];
        a += SIGMA_ * eps_z[bp*D_ + tid];
        sz[tid] = a;
        out[OFF_Z + bp*D_ + tid] = a;
    }
    __syncthreads();

    // h1 = relu(z @ W1 + b1)
    for (int f = tid; f < DFF_; f += 256) {
        float a = b1[f];
        #pragma unroll 8
        for (int d = 0; d < D_; ++d) a += sz[d] * W1[d*DFF_ + f];
        sh1[f] = fmaxf(a, 0.f);
    }
    __syncthreads();

    // r = h1 @ W2 + b2
    if (tid < D_) {
        float a = b2[tid];
        #pragma unroll 8
        for (int f = 0; f < DFF_; ++f) a += sh1[f] * W2[f*D_ + tid];
        sr[tid] = a;
        out[OFF_R + bp*D_ + tid] = a;
    }
    __syncthreads();

    // pred = r @ Wout + bout  (F == 1)
    if (tid == 0) {
        float a = bout[0];
        for (int d = 0; d < D_; ++d) a += sr[d] * Wout[d];
        g_pred[bp] = a;
        out[OFF_PRED + bp] = a;
    }
}

// ---------------------------------------------------------------------------
// Kernel 2: weights + categorical resampling. 16 blocks x 32 threads.
// ---------------------------------------------------------------------------
__global__ void resample_kernel(const float* __restrict__ y,
                                float* __restrict__ out)
{
    const int b = blockIdx.x;
    const int lane = threadIdx.x;
    __shared__ float slw[P_];

    float logw = 3.4e38f;               // min-reduce identity for inactive lanes
    if (lane < P_) {
        float mu = y[b*4] - g_pred[b*P_ + lane];   // y[b,0,0]
        logw = -0.5f * OMEGA_ * mu * mu;
    }
    float mn = logw;
    #pragma unroll
    for (int o = 16; o; o >>= 1) mn = fminf(mn, __shfl_xor_sync(0xffffffffu, mn, o));
    float w = (lane < P_) ? expf(logw - mn) : 0.f;
    float sum = w;
    #pragma unroll
    for (int o = 16; o; o >>= 1) sum += __shfl_xor_sync(0xffffffffu, sum, o);
    float wn = w / sum;
    if (lane < P_) {
        out[OFF_W + b*P_ + lane] = wn;
        slw[lane] = logf(wn + 1e-10f);
    }
    __syncwarp();

    const float tinyf = 1.1754943508222875e-38f;
    for (int p = 0; p < P_; ++p) {
        float g = -3.4e38f;
        if (lane < P_) {
            // flat gumbel index over shape (B, P, P)
            uint32_t i = (uint32_t)((b*P_ + p)*P_ + lane);
            // JAX partitionable threefry: per-element 64-bit counter (0, i),
            // 32-bit draw = o0 ^ o1
            uint32_t o0, o1;
            threefry_0_42(0u, i, o0, o1);
            uint32_t bits = o0 ^ o1;
            float u = __uint_as_float((bits >> 9) | 0x3f800000u) - 1.0f;
            u = u + tinyf;              // u*(1-tiny)+tiny, (1-tiny)==1 in f32
            u = fmaxf(tinyf, u);
            g = -logf(-logf(u)) + slw[lane];
        }
        int idx = lane;
        #pragma unroll
        for (int o = 16; o; o >>= 1) {
            float og = __shfl_xor_sync(0xffffffffu, g, o);
            int   oi = __shfl_xor_sync(0xffffffffu, idx, o);
            if (og > g || (og == g && oi < idx)) { g = og; idx = oi; }
        }
        if (lane == 0) g_idx[b*P_ + p] = idx;
    }
}

// ---------------------------------------------------------------------------
// Kernel 3: K_res / V_res gather copy. warp-per-row float4 copies.
// ---------------------------------------------------------------------------
__global__ void __launch_bounds__(256) copy_kv_kernel(
    const float* __restrict__ K, const float* __restrict__ V,
    const int* __restrict__ tp, float* __restrict__ out)
{
    const int t = tp ? tp[0] : 512;
    const int warp = threadIdx.x >> 5, lane = threadIdx.x & 31;
    const int r = blockIdx.x * 8 + warp;          // row index in [0, B*P*S)
    const int b   = r / (P_ * S_);
    const int rem = r - b * (P_ * S_);
    const int p   = rem >> 10;
    const int s   = rem & (S_ - 1);
    const int src = g_idx[b*P_ + p];

    const size_t srcrow = ((size_t)(b*P_ + src) * S_ + s) * D_;
    const float4* kp = (s == t)
        ? reinterpret_cast<const float4*>(g_knew + (b*P_ + src)*D_)
        : reinterpret_cast<const float4*>(K + srcrow);
    const float4* vp = (s == t)
        ? reinterpret_cast<const float4*>(g_vnew + (b*P_ + src)*D_)
        : reinterpret_cast<const float4*>(V + srcrow);

    float4* ok = reinterpret_cast<float4*>(out + OFF_K) + (size_t)r * 32;
    float4* ov = reinterpret_cast<float4*>(out + OFF_V) + (size_t)r * 32;
    ok[lane] = kp[lane];
    ov[lane] = vp[lane];
}

// ---------------------------------------------------------------------------
// Kernel 4: I_new gather (cast to float output).
// ---------------------------------------------------------------------------
__global__ void copy_i_kernel(const int* __restrict__ I,
                              const int* __restrict__ tp,
                              float* __restrict__ out)
{
    const int t = tp ? tp[0] : 512;
    const int gid = blockIdx.x * blockDim.x + threadIdx.x;
    if (gid >= B_*P_*S_) return;
    const int b   = gid / (P_ * S_);
    const int rem = gid - b * (P_ * S_);
    const int p   = rem >> 10;
    const int s   = rem & (S_ - 1);
    const int src = g_idx[b*P_ + p];
    const int val = (s == t) ? src : I[((size_t)(b*P_ + src)) * S_ + s];
    out[OFF_I + gid] = (float)val;
}

extern "C" void kernel_launch(void* const* d_in, const int* in_sizes, int n_in,
                              void* d_out, int out_size)
{
    const float* x     = (const float*)d_in[0];
    const float* y     = (const float*)d_in[1];
    const float* K     = (const float*)d_in[2];
    const float* V     = (const float*)d_in[3];
    /* w = d_in[4] unused */
    const int*   I     = (const int*)  d_in[5];
    const float* Wq    = (const float*)d_in[6];
    const float* Wk    = (const float*)d_in[7];
    const float* Wv    = (const float*)d_in[8];
    const float* Wo    = (const float*)d_in[9];
    const float* W1    = (const float*)d_in[10];
    const float* b1    = (const float*)d_in[11];
    const float* W2    = (const float*)d_in[12];
    const float* b2    = (const float*)d_in[13];
    const float* Wout  = (const float*)d_in[14];
    const float* bout  = (const float*)d_in[15];
    const float* eps_k = (const float*)d_in[16];
    const float* eps_v = (const float*)d_in[17];
    const float* eps_z = (const float*)d_in[18];
    const int*   tp    = (n_in > 19) ? (const int*)d_in[19] : nullptr;
    float* out = (float*)d_out;

    fwd_kernel<<<BP_, 256>>>(x, K, V, Wq, Wk, Wv, Wo, W1, b1, W2, b2,
                             Wout, bout, eps_k, eps_v, eps_z, tp, out);
    resample_kernel<<<B_, 32>>>(y, out);
    copy_kv_kernel<<<BP_ * S_ / 8, 256>>>(K, V, tp, out);
    copy_i_kernel<<<(B_*P_*S_ + 255)/256, 256>>>(I, tp, out);
}

// round 3
// speedup vs baseline: 1.4378x; 1.4378x over previous
#include <cuda_runtime.h>
#include <stdint.h>

#define B_ 16
#define P_ 25
#define S_ 1024
#define D_ 128
#define H_ 8
#define DH_ 16
#define DFF_ 512
#define BP_ (B_*P_)
#define SIGMA_ 0.1f
#define OMEGA_ 0.5f

// output layout (flat f32 concat of the reference tuple)
#define OFF_R    0
#define OFF_Z    51200
#define OFF_PRED 102400
#define OFF_W    102800
#define OFF_K    103200
#define OFF_V    52532000
#define OFF_I    104960800

// scratch (allocation-free: __device__ globals)
__device__ __align__(16) float g_knew[BP_*D_];
__device__ __align__(16) float g_vnew[BP_*D_];
__device__ float g_pred[BP_];
__device__ int   g_idx[BP_];

__device__ __forceinline__ uint32_t rotl32(uint32_t x, int d) {
    return (x << d) | (x >> (32 - d));
}

// Threefry-2x32 with key (0, 42)  [jax.random.key(42)]
__device__ __forceinline__ void threefry_0_42(uint32_t x0, uint32_t x1,
                                              uint32_t& o0, uint32_t& o1) {
    const uint32_t k0 = 0u, k1 = 42u;
    const uint32_t k2 = k0 ^ k1 ^ 0x1BD11BDAu;
    uint32_t v0 = x0 + k0, v1 = x1 + k1;
#define TF_R(r) { v0 += v1; v1 = rotl32(v1, r); v1 ^= v0; }
    TF_R(13) TF_R(15) TF_R(26) TF_R(6)
    v0 += k1; v1 += k2 + 1u;
    TF_R(17) TF_R(29) TF_R(16) TF_R(24)
    v0 += k2; v1 += k0 + 2u;
    TF_R(13) TF_R(15) TF_R(26) TF_R(6)
    v0 += k0; v1 += k1 + 3u;
    TF_R(17) TF_R(29) TF_R(16) TF_R(24)
    v0 += k1; v1 += k2 + 4u;
    TF_R(13) TF_R(15) TF_R(26) TF_R(6)
    v0 += k2; v1 += k0 + 5u;
#undef TF_R
    o0 = v0; o1 = v1;
}

// ---------------------------------------------------------------------------
// Kernel 1: per-(b,p) forward. 400 blocks x 512 threads.
// Every phase is split 4 ways so each thread's serial dependency chain is
// ~128 MACs / ~128 loads max.
// ---------------------------------------------------------------------------
__global__ void __launch_bounds__(512) fwd_kernel(
    const float* __restrict__ x, const float* __restrict__ K,
    const float* __restrict__ V,
    const float* __restrict__ Wq, const float* __restrict__ Wk,
    const float* __restrict__ Wv, const float* __restrict__ Wo,
    const float* __restrict__ W1, const float* __restrict__ b1,
    const float* __restrict__ W2, const float* __restrict__ b2,
    const float* __restrict__ Wout, const float* __restrict__ bout,
    const float* __restrict__ eps_k, const float* __restrict__ eps_v,
    const float* __restrict__ eps_z,
    const int* __restrict__ tp, float* __restrict__ out)
{
    __shared__ float sx[D_], sq[D_], sk[D_], sv[D_];
    __shared__ float sS[H_][S_];
    __shared__ float sred[4][D_];        // 4-way partial reductions
    __shared__ float sctx[D_], sz[D_], sh1[DFF_], sr[D_];

    const int bp  = blockIdx.x;
    const int tid = threadIdx.x;
    const int dim = tid & 127;
    const int grp = tid >> 7;            // 0..3
    const int t   = tp ? tp[0] : 512;

    if (tid < D_) sx[tid] = x[bp*D_ + tid];
    __syncthreads();

    // q, k, v projections: groups 0/1/2 each handle one matrix (128 MACs/thr)
    if (grp < 3) {
        const float* W = (grp == 0) ? Wq : (grp == 1) ? Wk : Wv;
        float a = 0.f;
        #pragma unroll 8
        for (int d = 0; d < D_; ++d) a += sx[d] * W[d*D_ + dim];
        if (grp == 0) {
            sq[dim] = a;
        } else if (grp == 1) {
            a += SIGMA_ * eps_k[bp*D_ + dim];
            sk[dim] = a; g_knew[bp*D_ + dim] = a;
        } else {
            a += SIGMA_ * eps_v[bp*D_ + dim];
            sv[dim] = a; g_vnew[bp*D_ + dim] = a;
        }
    }
    __syncthreads();

    // scores for s in [0, t): one K row (512B) per thread
    const float4* Kbase = reinterpret_cast<const float4*>(K + (size_t)bp * S_ * D_);
    for (int s = tid; s < t; s += 512) {
        const float4* kr = Kbase + (size_t)s * 32;
        float acc[H_];
        #pragma unroll
        for (int h = 0; h < H_; ++h) acc[h] = 0.f;
        #pragma unroll
        for (int i = 0; i < 32; ++i) {
            float4 kv = kr[i];
            int h = i >> 2;
            acc[h] += sq[4*i+0]*kv.x + sq[4*i+1]*kv.y + sq[4*i+2]*kv.z + sq[4*i+3]*kv.w;
        }
        #pragma unroll
        for (int h = 0; h < H_; ++h) sS[h][s] = acc[h] * 0.25f;
    }
    // s == t uses the freshly computed k
    if (tid < H_) {
        float a = 0.f;
        #pragma unroll
        for (int d = 0; d < DH_; ++d) a += sq[tid*DH_ + d] * sk[tid*DH_ + d];
        sS[tid][t] = a * 0.25f;
    }
    __syncthreads();

    // softmax per head (warp h handles head h; warps 8..15 idle)
    if (tid < 256) {
        int h = tid >> 5, lane = tid & 31;
        float m = -3.4e38f;
        for (int s = lane; s <= t; s += 32) m = fmaxf(m, sS[h][s]);
        #pragma unroll
        for (int o = 16; o; o >>= 1) m = fmaxf(m, __shfl_xor_sync(0xffffffffu, m, o));
        float sum = 0.f;
        for (int s = lane; s <= t; s += 32) {
            float e = expf(sS[h][s] - m);
            sS[h][s] = e; sum += e;
        }
        #pragma unroll
        for (int o = 16; o; o >>= 1) sum += __shfl_xor_sync(0xffffffffu, sum, o);
        float inv = 1.f / sum;
        for (int s = lane; s <= t; s += 32) sS[h][s] *= inv;
    }
    __syncthreads();

    // ctx: 4-way split over s; V reads coalesced over dim
    {
        int h = dim >> 4;
        const float* Vrow = V + (size_t)bp * S_ * D_ + dim;
        float c = 0.f;
        for (int s = grp; s <= t; s += 4) {
            float vv = (s == t) ? sv[dim] : Vrow[(size_t)s * D_];
            c += sS[h][s] * vv;
        }
        sred[grp][dim] = c;
    }
    __syncthreads();
    if (tid < D_) sctx[tid] = sred[0][tid] + sred[1][tid] + sred[2][tid] + sred[3][tid];
    __syncthreads();

    // z = ctx @ Wo + sigma*eps_z   (4-way split over the 128-dim contraction)
    {
        float a = 0.f;
        #pragma unroll
        for (int d = grp*32; d < grp*32 + 32; ++d) a += sctx[d] * Wo[d*D_ + dim];
        sred[grp][dim] = a;
    }
    __syncthreads();
    if (tid < D_) {
        float a = sred[0][tid] + sred[1][tid] + sred[2][tid] + sred[3][tid]
                + SIGMA_ * eps_z[bp*D_ + tid];
        sz[tid] = a;
        out[OFF_Z + bp*D_ + tid] = a;
    }
    __syncthreads();

    // h1 = relu(z @ W1 + b1): one output per thread (128 MACs)
    {
        float a = b1[tid];
        #pragma unroll 8
        for (int d = 0; d < D_; ++d) a += sz[d] * W1[d*DFF_ + tid];
        sh1[tid] = fmaxf(a, 0.f);
    }
    __syncthreads();

    // r = h1 @ W2 + b2: 4-way split over the 512-dim contraction
    {
        float a = 0.f;
        #pragma unroll 8
        for (int f = grp*128; f < grp*128 + 128; ++f) a += sh1[f] * W2[f*D_ + dim];
        sred[grp][dim] = a;
    }
    __syncthreads();
    if (tid < D_) {
        float a = b2[tid] + sred[0][tid] + sred[1][tid] + sred[2][tid] + sred[3][tid];
        sr[tid] = a;
        out[OFF_R + bp*D_ + tid] = a;
    }
    __syncthreads();

    // pred = r @ Wout + bout  (F == 1): warp 0 reduce
    if (tid < 32) {
        float a = 0.f;
        #pragma unroll
        for (int d = tid; d < D_; d += 32) a += sr[d] * Wout[d];
        #pragma unroll
        for (int o = 16; o; o >>= 1) a += __shfl_xor_sync(0xffffffffu, a, o);
        if (tid == 0) {
            a += bout[0];
            g_pred[bp] = a;
            out[OFF_PRED + bp] = a;
        }
    }
}

// ---------------------------------------------------------------------------
// Kernel 2: weights + categorical resampling. 16 blocks x 32 threads.
// ---------------------------------------------------------------------------
__global__ void resample_kernel(const float* __restrict__ y,
                                float* __restrict__ out)
{
    const int b = blockIdx.x;
    const int lane = threadIdx.x;
    __shared__ float slw[P_];

    float logw = 3.4e38f;               // min-reduce identity for inactive lanes
    if (lane < P_) {
        float mu = y[b*4] - g_pred[b*P_ + lane];   // y[b,0,0]
        logw = -0.5f * OMEGA_ * mu * mu;
    }
    float mn = logw;
    #pragma unroll
    for (int o = 16; o; o >>= 1) mn = fminf(mn, __shfl_xor_sync(0xffffffffu, mn, o));
    float w = (lane < P_) ? expf(logw - mn) : 0.f;
    float sum = w;
    #pragma unroll
    for (int o = 16; o; o >>= 1) sum += __shfl_xor_sync(0xffffffffu, sum, o);
    float wn = w / sum;
    if (lane < P_) {
        out[OFF_W + b*P_ + lane] = wn;
        slw[lane] = logf(wn + 1e-10f);
    }
    __syncwarp();

    const float tinyf = 1.1754943508222875e-38f;
    for (int p = 0; p < P_; ++p) {
        float g = -3.4e38f;
        if (lane < P_) {
            uint32_t i = (uint32_t)((b*P_ + p)*P_ + lane);
            uint32_t o0, o1;
            threefry_0_42(0u, i, o0, o1);
            uint32_t bits = o0 ^ o1;
            float u = __uint_as_float((bits >> 9) | 0x3f800000u) - 1.0f;
            u = u + tinyf;
            u = fmaxf(tinyf, u);
            g = -logf(-logf(u)) + slw[lane];
        }
        int idx = lane;
        #pragma unroll
        for (int o = 16; o; o >>= 1) {
            float og = __shfl_xor_sync(0xffffffffu, g, o);
            int   oi = __shfl_xor_sync(0xffffffffu, idx, o);
            if (og > g || (og == g && oi < idx)) { g = og; idx = oi; }
        }
        if (lane == 0) g_idx[b*P_ + p] = idx;
    }
}

// ---------------------------------------------------------------------------
// Kernel 3: K_res / V_res gather copy. warp-per-row float4 copies.
// Grid is (b, s, p)-major so particles sharing an ancestor hit the same
// source row back-to-back (L2/L1 reuse on the gather reads).
// ---------------------------------------------------------------------------
__global__ void __launch_bounds__(256) copy_kv_kernel(
    const float* __restrict__ K, const float* __restrict__ V,
    const int* __restrict__ tp, float* __restrict__ out)
{
    const int t = tp ? tp[0] : 512;
    const int warp = threadIdx.x >> 5, lane = threadIdx.x & 31;
    const int q = blockIdx.x * 8 + warp;          // enumerates (b, s, p)
    const int b   = q / (S_ * P_);
    const int rem = q - b * (S_ * P_);
    const int s   = rem / P_;
    const int p   = rem - s * P_;
    const int src = g_idx[b*P_ + p];

    const size_t srcrow = ((size_t)(b*P_ + src) * S_ + s) * D_;
    const float4* kp = (s == t)
        ? reinterpret_cast<const float4*>(g_knew + (b*P_ + src)*D_)
        : reinterpret_cast<const float4*>(K + srcrow);
    const float4* vp = (s == t)
        ? reinterpret_cast<const float4*>(g_vnew + (b*P_ + src)*D_)
        : reinterpret_cast<const float4*>(V + srcrow);

    const size_t dstrow = ((size_t)(b*P_ + p) * S_ + s) * 32;
    float4* ok = reinterpret_cast<float4*>(out + OFF_K) + dstrow;
    float4* ov = reinterpret_cast<float4*>(out + OFF_V) + dstrow;
    ok[lane] = kp[lane];
    ov[lane] = vp[lane];
}

// ---------------------------------------------------------------------------
// Kernel 4: I_new gather (cast to float output).
// ---------------------------------------------------------------------------
__global__ void copy_i_kernel(const int* __restrict__ I,
                              const int* __restrict__ tp,
                              float* __restrict__ out)
{
    const int t = tp ? tp[0] : 512;
    const int gid = blockIdx.x * blockDim.x + threadIdx.x;
    if (gid >= B_*P_*S_) return;
    const int b   = gid / (P_ * S_);
    const int rem = gid - b * (P_ * S_);
    const int p   = rem >> 10;
    const int s   = rem & (S_ - 1);
    const int src = g_idx[b*P_ + p];
    const int val = (s == t) ? src : I[((size_t)(b*P_ + src)) * S_ + s];
    out[OFF_I + gid] = (float)val;
}

extern "C" void kernel_launch(void* const* d_in, const int* in_sizes, int n_in,
                              void* d_out, int out_size)
{
    const float* x     = (const float*)d_in[0];
    const float* y     = (const float*)d_in[1];
    const float* K     = (const float*)d_in[2];
    const float* V     = (const float*)d_in[3];
    /* w = d_in[4] unused */
    const int*   I     = (const int*)  d_in[5];
    const float* Wq    = (const float*)d_in[6];
    const float* Wk    = (const float*)d_in[7];
    const float* Wv    = (const float*)d_in[8];
    const float* Wo    = (const float*)d_in[9];
    const float* W1    = (const float*)d_in[10];
    const float* b1    = (const float*)d_in[11];
    const float* W2    = (const float*)d_in[12];
    const float* b2    = (const float*)d_in[13];
    const float* Wout  = (const float*)d_in[14];
    const float* bout  = (const float*)d_in[15];
    const float* eps_k = (const float*)d_in[16];
    const float* eps_v = (const float*)d_in[17];
    const float* eps_z = (const float*)d_in[18];
    const int*   tp    = (n_in > 19) ? (const int*)d_in[19] : nullptr;
    float* out = (float*)d_out;

    fwd_kernel<<<BP_, 512>>>(x, K, V, Wq, Wk, Wv, Wo, W1, b1, W2, b2,
                             Wout, bout, eps_k, eps_v, eps_z, tp, out);
    resample_kernel<<<B_, 32>>>(y, out);
    copy_kv_kernel<<<BP_ * S_ / 8, 256>>>(K, V, tp, out);
    copy_i_kernel<<<(B_*P_*S_ + 255)/256, 256>>>(I, tp, out);
}

// round 4
// speedup vs baseline: 1.9453x; 1.3530x over previous
#include <cuda_runtime.h>
#include <stdint.h>

#define B_ 16
#define P_ 25
#define S_ 1024
#define D_ 128
#define H_ 8
#define DH_ 16
#define DFF_ 512
#define BP_ (B_*P_)
#define SIGMA_ 0.1f
#define OMEGA_ 0.5f

// output layout (flat f32 concat of the reference tuple)
#define OFF_R    0
#define OFF_Z    51200
#define OFF_PRED 102400
#define OFF_W    102800
#define OFF_K    103200
#define OFF_V    52532000
#define OFF_I    104960800

// scratch (allocation-free: __device__ globals)
__device__ __align__(16) float g_knew[BP_*D_];
__device__ __align__(16) float g_vnew[BP_*D_];
__device__ float g_pred[BP_];
__device__ int   g_idx[BP_];

__device__ __forceinline__ uint32_t rotl32(uint32_t x, int d) {
    return (x << d) | (x >> (32 - d));
}

// Threefry-2x32 with key (0, 42)  [jax.random.key(42)]
__device__ __forceinline__ void threefry_0_42(uint32_t x0, uint32_t x1,
                                              uint32_t& o0, uint32_t& o1) {
    const uint32_t k0 = 0u, k1 = 42u;
    const uint32_t k2 = k0 ^ k1 ^ 0x1BD11BDAu;
    uint32_t v0 = x0 + k0, v1 = x1 + k1;
#define TF_R(r) { v0 += v1; v1 = rotl32(v1, r); v1 ^= v0; }
    TF_R(13) TF_R(15) TF_R(26) TF_R(6)
    v0 += k1; v1 += k2 + 1u;
    TF_R(17) TF_R(29) TF_R(16) TF_R(24)
    v0 += k2; v1 += k0 + 2u;
    TF_R(13) TF_R(15) TF_R(26) TF_R(6)
    v0 += k0; v1 += k1 + 3u;
    TF_R(17) TF_R(29) TF_R(16) TF_R(24)
    v0 += k1; v1 += k2 + 4u;
    TF_R(13) TF_R(15) TF_R(26) TF_R(6)
    v0 += k2; v1 += k0 + 5u;
#undef TF_R
    o0 = v0; o1 = v1;
}

// ---------------------------------------------------------------------------
// Kernel 1: per-(b,p) forward. 400 blocks x 512 threads.
// Scores phase: warp-per-row, fully coalesced K reads + shfl head-reduce.
// ---------------------------------------------------------------------------
__global__ void __launch_bounds__(512) fwd_kernel(
    const float* __restrict__ x, const float* __restrict__ K,
    const float* __restrict__ V,
    const float* __restrict__ Wq, const float* __restrict__ Wk,
    const float* __restrict__ Wv, const float* __restrict__ Wo,
    const float* __restrict__ W1, const float* __restrict__ b1,
    const float* __restrict__ W2, const float* __restrict__ b2,
    const float* __restrict__ Wout, const float* __restrict__ bout,
    const float* __restrict__ eps_k, const float* __restrict__ eps_v,
    const float* __restrict__ eps_z,
    const int* __restrict__ tp, float* __restrict__ out)
{
    __shared__ float sx[D_], sq[D_], sk[D_], sv[D_];
    __shared__ float sS[H_][S_];
    __shared__ float sred[4][D_];        // 4-way partial reductions
    __shared__ float sctx[D_], sz[D_], sh1[DFF_], sr[D_];

    const int bp   = blockIdx.x;
    const int tid  = threadIdx.x;
    const int dim  = tid & 127;
    const int grp  = tid >> 7;           // 0..3
    const int warp = tid >> 5;           // 0..15
    const int lane = tid & 31;
    const int t    = tp ? tp[0] : 512;

    if (tid < D_) sx[tid] = x[bp*D_ + tid];
    __syncthreads();

    // q, k, v projections: groups 0/1/2 each handle one matrix (128 MACs/thr)
    if (grp < 3) {
        const float* W = (grp == 0) ? Wq : (grp == 1) ? Wk : Wv;
        float a = 0.f;
        #pragma unroll 8
        for (int d = 0; d < D_; ++d) a += sx[d] * W[d*D_ + dim];
        if (grp == 0) {
            sq[dim] = a;
        } else if (grp == 1) {
            a += SIGMA_ * eps_k[bp*D_ + dim];
            sk[dim] = a; g_knew[bp*D_ + dim] = a;
        } else {
            a += SIGMA_ * eps_v[bp*D_ + dim];
            sv[dim] = a; g_vnew[bp*D_ + dim] = a;
        }
    }
    __syncthreads();

    // scores for s in [0, t): warp-per-row, lane owns 4 contiguous dims.
    {
        const float4* Kbase = reinterpret_cast<const float4*>(K + (size_t)bp * S_ * D_);
        const float4  qf    = reinterpret_cast<const float4*>(sq)[lane];
        const int     head  = lane >> 2;
        #pragma unroll 2
        for (int s = warp; s < t; s += 16) {
            float4 kv = Kbase[(size_t)s * 32 + lane];
            float a = qf.x*kv.x + qf.y*kv.y + qf.z*kv.z + qf.w*kv.w;
            a += __shfl_xor_sync(0xffffffffu, a, 1);
            a += __shfl_xor_sync(0xffffffffu, a, 2);
            if ((lane & 3) == 0) sS[head][s] = a * 0.25f;
        }
    }
    // s == t uses the freshly computed k
    if (tid < H_) {
        float a = 0.f;
        #pragma unroll
        for (int d = 0; d < DH_; ++d) a += sq[tid*DH_ + d] * sk[tid*DH_ + d];
        sS[tid][t] = a * 0.25f;
    }
    __syncthreads();

    // softmax per head (warp h handles head h; warps 8..15 idle)
    if (tid < 256) {
        int h = tid >> 5, ln = tid & 31;
        float m = -3.4e38f;
        for (int s = ln; s <= t; s += 32) m = fmaxf(m, sS[h][s]);
        #pragma unroll
        for (int o = 16; o; o >>= 1) m = fmaxf(m, __shfl_xor_sync(0xffffffffu, m, o));
        float sum = 0.f;
        for (int s = ln; s <= t; s += 32) {
            float e = expf(sS[h][s] - m);
            sS[h][s] = e; sum += e;
        }
        #pragma unroll
        for (int o = 16; o; o >>= 1) sum += __shfl_xor_sync(0xffffffffu, sum, o);
        float inv = 1.f / sum;
        for (int s = ln; s <= t; s += 32) sS[h][s] *= inv;
    }
    __syncthreads();

    // ctx: 4-way split over s; V reads coalesced over dim; unrolled for MLP
    {
        int h = dim >> 4;
        const float* Vrow = V + (size_t)bp * S_ * D_ + dim;
        float c0 = 0.f, c1 = 0.f, c2 = 0.f, c3 = 0.f;
        int s = grp;
        for (; s + 12 < t; s += 16) {
            float v0 = Vrow[(size_t)(s     ) * D_];
            float v1 = Vrow[(size_t)(s +  4) * D_];
            float v2 = Vrow[(size_t)(s +  8) * D_];
            float v3 = Vrow[(size_t)(s + 12) * D_];
            c0 += sS[h][s     ] * v0;
            c1 += sS[h][s +  4] * v1;
            c2 += sS[h][s +  8] * v2;
            c3 += sS[h][s + 12] * v3;
        }
        for (; s <= t; s += 4) {
            float vv = (s == t) ? sv[dim] : Vrow[(size_t)s * D_];
            c0 += sS[h][s] * vv;
        }
        sred[grp][dim] = (c0 + c1) + (c2 + c3);
    }
    __syncthreads();
    if (tid < D_) sctx[tid] = sred[0][tid] + sred[1][tid] + sred[2][tid] + sred[3][tid];
    __syncthreads();

    // z = ctx @ Wo + sigma*eps_z   (4-way split over the 128-dim contraction)
    {
        float a = 0.f;
        #pragma unroll
        for (int d = grp*32; d < grp*32 + 32; ++d) a += sctx[d] * Wo[d*D_ + dim];
        sred[grp][dim] = a;
    }
    __syncthreads();
    if (tid < D_) {
        float a = sred[0][tid] + sred[1][tid] + sred[2][tid] + sred[3][tid]
                + SIGMA_ * eps_z[bp*D_ + tid];
        sz[tid] = a;
        out[OFF_Z + bp*D_ + tid] = a;
    }
    __syncthreads();

    // h1 = relu(z @ W1 + b1): one output per thread (128 MACs)
    {
        float a = b1[tid];
        #pragma unroll 8
        for (int d = 0; d < D_; ++d) a += sz[d] * W1[d*DFF_ + tid];
        sh1[tid] = fmaxf(a, 0.f);
    }
    __syncthreads();

    // r = h1 @ W2 + b2: 4-way split over the 512-dim contraction
    {
        float a = 0.f;
        #pragma unroll 8
        for (int f = grp*128; f < grp*128 + 128; ++f) a += sh1[f] * W2[f*D_ + dim];
        sred[grp][dim] = a;
    }
    __syncthreads();
    if (tid < D_) {
        float a = b2[tid] + sred[0][tid] + sred[1][tid] + sred[2][tid] + sred[3][tid];
        sr[tid] = a;
        out[OFF_R + bp*D_ + tid] = a;
    }
    __syncthreads();

    // pred = r @ Wout + bout  (F == 1): warp 0 reduce
    if (tid < 32) {
        float a = 0.f;
        #pragma unroll
        for (int d = tid; d < D_; d += 32) a += sr[d] * Wout[d];
        #pragma unroll
        for (int o = 16; o; o >>= 1) a += __shfl_xor_sync(0xffffffffu, a, o);
        if (tid == 0) {
            a += bout[0];
            g_pred[bp] = a;
            out[OFF_PRED + bp] = a;
        }
    }
}

// ---------------------------------------------------------------------------
// Kernel 2: weights + categorical resampling. 16 blocks x 32 threads.
// ---------------------------------------------------------------------------
__global__ void resample_kernel(const float* __restrict__ y,
                                float* __restrict__ out)
{
    const int b = blockIdx.x;
    const int lane = threadIdx.x;
    __shared__ float slw[P_];

    float logw = 3.4e38f;               // min-reduce identity for inactive lanes
    if (lane < P_) {
        float mu = y[b*4] - g_pred[b*P_ + lane];   // y[b,0,0]
        logw = -0.5f * OMEGA_ * mu * mu;
    }
    float mn = logw;
    #pragma unroll
    for (int o = 16; o; o >>= 1) mn = fminf(mn, __shfl_xor_sync(0xffffffffu, mn, o));
    float w = (lane < P_) ? expf(logw - mn) : 0.f;
    float sum = w;
    #pragma unroll
    for (int o = 16; o; o >>= 1) sum += __shfl_xor_sync(0xffffffffu, sum, o);
    float wn = w / sum;
    if (lane < P_) {
        out[OFF_W + b*P_ + lane] = wn;
        slw[lane] = logf(wn + 1e-10f);
    }
    __syncwarp();

    const float tinyf = 1.1754943508222875e-38f;
    for (int p = 0; p < P_; ++p) {
        float g = -3.4e38f;
        if (lane < P_) {
            uint32_t i = (uint32_t)((b*P_ + p)*P_ + lane);
            uint32_t o0, o1;
            threefry_0_42(0u, i, o0, o1);
            uint32_t bits = o0 ^ o1;
            float u = __uint_as_float((bits >> 9) | 0x3f800000u) - 1.0f;
            u = u + tinyf;
            u = fmaxf(tinyf, u);
            g = -logf(-logf(u)) + slw[lane];
        }
        int idx = lane;
        #pragma unroll
        for (int o = 16; o; o >>= 1) {
            float og = __shfl_xor_sync(0xffffffffu, g, o);
            int   oi = __shfl_xor_sync(0xffffffffu, idx, o);
            if (og > g || (og == g && oi < idx)) { g = og; idx = oi; }
        }
        if (lane == 0) g_idx[b*P_ + p] = idx;
    }
}

// ---------------------------------------------------------------------------
// Kernel 3: K_res / V_res gather copy. 4 rows per warp, loads batched into
// registers before any store (MLP 8). Grid is (b, s, p)-major so particles
// sharing an ancestor hit the same source row back-to-back (L2 reuse).
// ---------------------------------------------------------------------------
__global__ void __launch_bounds__(256) copy_kv_kernel(
    const float* __restrict__ K, const float* __restrict__ V,
    const int* __restrict__ tp, float* __restrict__ out)
{
    const int t = tp ? tp[0] : 512;
    const int warp = threadIdx.x >> 5, lane = threadIdx.x & 31;
    const int q0 = (blockIdx.x * 8 + warp) * 4;   // enumerates (b, s, p)

    const float4* kp[4];
    const float4* vp[4];
    size_t dst[4];
    #pragma unroll
    for (int j = 0; j < 4; ++j) {
        int q   = q0 + j;
        int b   = q / (S_ * P_);
        int rem = q - b * (S_ * P_);
        int s   = rem / P_;
        int p   = rem - s * P_;
        int src = g_idx[b*P_ + p];
        size_t srcrow = ((size_t)(b*P_ + src) * S_ + s) * 32;
        if (s == t) {
            kp[j] = reinterpret_cast<const float4*>(g_knew + (b*P_ + src)*D_);
            vp[j] = reinterpret_cast<const float4*>(g_vnew + (b*P_ + src)*D_);
        } else {
            kp[j] = reinterpret_cast<const float4*>(K) + srcrow;
            vp[j] = reinterpret_cast<const float4*>(V) + srcrow;
        }
        dst[j] = ((size_t)(b*P_ + p) * S_ + s) * 32;
    }

    float4 kr[4], vr[4];
    #pragma unroll
    for (int j = 0; j < 4; ++j) kr[j] = kp[j][lane];
    #pragma unroll
    for (int j = 0; j < 4; ++j) vr[j] = vp[j][lane];

    float4* ok = reinterpret_cast<float4*>(out + OFF_K);
    float4* ov = reinterpret_cast<float4*>(out + OFF_V);
    #pragma unroll
    for (int j = 0; j < 4; ++j) ok[dst[j] + lane] = kr[j];
    #pragma unroll
    for (int j = 0; j < 4; ++j) ov[dst[j] + lane] = vr[j];
}

// ---------------------------------------------------------------------------
// Kernel 4: I_new gather (cast to float output).
// ---------------------------------------------------------------------------
__global__ void copy_i_kernel(const int* __restrict__ I,
                              const int* __restrict__ tp,
                              float* __restrict__ out)
{
    const int t = tp ? tp[0] : 512;
    const int gid = blockIdx.x * blockDim.x + threadIdx.x;
    if (gid >= B_*P_*S_) return;
    const int b   = gid / (P_ * S_);
    const int rem = gid - b * (P_ * S_);
    const int p   = rem >> 10;
    const int s   = rem & (S_ - 1);
    const int src = g_idx[b*P_ + p];
    const int val = (s == t) ? src : I[((size_t)(b*P_ + src)) * S_ + s];
    out[OFF_I + gid] = (float)val;
}

extern "C" void kernel_launch(void* const* d_in, const int* in_sizes, int n_in,
                              void* d_out, int out_size)
{
    const float* x     = (const float*)d_in[0];
    const float* y     = (const float*)d_in[1];
    const float* K     = (const float*)d_in[2];
    const float* V     = (const float*)d_in[3];
    /* w = d_in[4] unused */
    const int*   I     = (const int*)  d_in[5];
    const float* Wq    = (const float*)d_in[6];
    const float* Wk    = (const float*)d_in[7];
    const float* Wv    = (const float*)d_in[8];
    const float* Wo    = (const float*)d_in[9];
    const float* W1    = (const float*)d_in[10];
    const float* b1    = (const float*)d_in[11];
    const float* W2    = (const float*)d_in[12];
    const float* b2    = (const float*)d_in[13];
    const float* Wout  = (const float*)d_in[14];
    const float* bout  = (const float*)d_in[15];
    const float* eps_k = (const float*)d_in[16];
    const float* eps_v = (const float*)d_in[17];
    const float* eps_z = (const float*)d_in[18];
    const int*   tp    = (n_in > 19) ? (const int*)d_in[19] : nullptr;
    float* out = (float*)d_out;

    fwd_kernel<<<BP_, 512>>>(x, K, V, Wq, Wk, Wv, Wo, W1, b1, W2, b2,
                             Wout, bout, eps_k, eps_v, eps_z, tp, out);
    resample_kernel<<<B_, 32>>>(y, out);
    copy_i_kernel<<<(B_*P_*S_ + 255)/256, 256>>>(I, tp, out);
    copy_kv_kernel<<<BP_ * S_ / 32, 256>>>(K, V, tp, out);
}